// round 9
// baseline (speedup 1.0000x reference)
#include <cuda_runtime.h>
#include <cuda_bf16.h>
#include <math.h>
#include <cstdint>

#define NN 50000
#define EE 800000
#define ETOT (EE + NN)   // edges + self loops
#define NH 8
#define NBLK 196         // ceil(NN/256)

// ---------------- scratch (device globals; no runtime allocation) ----------------
__device__ float g_h0  [NN * 256];
__device__ float g_h   [NN * 256];
__device__ float g_hp  [NN * 256];
__device__ float g_ssrc[NN * NH];
__device__ float g_sdst[NN * NH];
__device__ float g_emb [NN * 3 * 256];
__device__ float g_hid [NN * 3 * 128];
__device__ float g_z   [NN * 256];
__device__ float g_hcls[NN * 128];
// transposed+split weights [N][K]: proj @0 (256x128), gat pl (256x256) @32768+pl*65536,
// sem (128x256) @425984, cls (128x256) @458752
__device__ __align__(16) __nv_bfloat16 g_whi[491520];
__device__ __align__(16) __nv_bfloat16 g_wlo[491520];
// CSR
__device__ int g_rowptr[3 * (NN + 1)];
__device__ int g_colidx[3 * ETOT];
__device__ int g_deg   [NN];
__device__ int g_cursor[NN];
__device__ int g_bsum  [256];
__device__ int g_boff  [256];

// ---------------- warp-MMA helpers (plain sm_80+ PTX) ----------------
__device__ __forceinline__ uint32_t smem_u32(const void* p) {
    uint32_t a;
    asm("{ .reg .u64 t; cvta.to.shared.u64 t, %1; cvt.u32.u64 %0, t; }" : "=r"(a) : "l"(p));
    return a;
}
__device__ __forceinline__ void ldsm_x4(uint32_t* r, uint32_t addr) {
    asm volatile("ldmatrix.sync.aligned.m8n8.x4.shared.b16 {%0,%1,%2,%3}, [%4];"
                 : "=r"(r[0]), "=r"(r[1]), "=r"(r[2]), "=r"(r[3]) : "r"(addr));
}
__device__ __forceinline__ void ldsm_x2(uint32_t* r, uint32_t addr) {
    asm volatile("ldmatrix.sync.aligned.m8n8.x2.shared.b16 {%0,%1}, [%2];"
                 : "=r"(r[0]), "=r"(r[1]) : "r"(addr));
}
__device__ __forceinline__ void mma_bf16(float* c, const uint32_t* a, const uint32_t* b) {
    asm volatile("mma.sync.aligned.m16n8k16.row.col.f32.bf16.bf16.f32 "
                 "{%0,%1,%2,%3}, {%4,%5,%6,%7}, {%8,%9}, {%0,%1,%2,%3};"
                 : "+f"(c[0]), "+f"(c[1]), "+f"(c[2]), "+f"(c[3])
                 : "r"(a[0]), "r"(a[1]), "r"(a[2]), "r"(a[3]), "r"(b[0]), "r"(b[1]));
}
__device__ __forceinline__ void split_pack(const float* v, uint32_t* ph, uint32_t* pl) {
#pragma unroll
    for (int j = 0; j < 4; j++) {
        const __nv_bfloat16 h0 = __float2bfloat16(v[2 * j]);
        const __nv_bfloat16 h1 = __float2bfloat16(v[2 * j + 1]);
        const __nv_bfloat16 l0 = __float2bfloat16(v[2 * j] - __bfloat162float(h0));
        const __nv_bfloat16 l1 = __float2bfloat16(v[2 * j + 1] - __bfloat162float(h1));
        ph[j] = (uint32_t)__bfloat16_as_ushort(h0) | ((uint32_t)__bfloat16_as_ushort(h1) << 16);
        pl[j] = (uint32_t)__bfloat16_as_ushort(l0) | ((uint32_t)__bfloat16_as_ushort(l1) << 16);
    }
}

// ---------------- bf16-split tensor GEMM (fp32 A, split staged in smem) ----------------
// C[M,Nc] = act(A @ W + bias). A fp32 [M,K] row-major; W transposed+split bf16 [Nc][K].
// D ~= Ahi*Bhi + Ahi*Blo + Alo*Bhi, fp32 accum. Nc%128==0, K%32==0.
#define LDSE 40
#define PLANE (128 * LDSE * 2)
template <int ACT>   // 0 none, 1 tanh, 2 relu
__global__ void __launch_bounds__(256, 1)
gemm_mma(const float* __restrict__ A,
         const __nv_bfloat16* __restrict__ Bhi, const __nv_bfloat16* __restrict__ Blo,
         const float* __restrict__ bias, float* __restrict__ C,
         int M, int K, int Nc) {
    __shared__ __align__(16) __nv_bfloat16 sA[2][128][LDSE];
    __shared__ __align__(16) __nv_bfloat16 sB[2][128][LDSE];
    const int tid = threadIdx.x;
    const int lane = tid & 31;
    const int w = tid >> 5;
    const int wm = w & 3, wn = w >> 2;
    const int rowBase = blockIdx.y * 128;
    const int colBase = blockIdx.x * 128;

    float acc[2][8][4];
#pragma unroll
    for (int i = 0; i < 2; i++)
#pragma unroll
        for (int j = 0; j < 8; j++)
#pragma unroll
            for (int e = 0; e < 4; e++) acc[i][j][e] = 0.f;

    const uint32_t sAu = smem_u32(&sA[0][0][0]);
    const uint32_t sBu = smem_u32(&sB[0][0][0]);

    for (int k0 = 0; k0 < K; k0 += 32) {
#pragma unroll
        for (int t = 0; t < 2; t++) {
            const int idx = tid + t * 256;        // 0..511
            const int row = idx >> 2;
            const int c8 = (idx & 3) * 8;         // element offset within 32-elem row
            const int grow = rowBase + row;
            float v[8];
            if (grow < M) {
                const float4 f0 = *(const float4*)(A + (size_t)grow * K + k0 + c8);
                const float4 f1 = *(const float4*)(A + (size_t)grow * K + k0 + c8 + 4);
                v[0] = f0.x; v[1] = f0.y; v[2] = f0.z; v[3] = f0.w;
                v[4] = f1.x; v[5] = f1.y; v[6] = f1.z; v[7] = f1.w;
            } else {
#pragma unroll
                for (int j = 0; j < 8; j++) v[j] = 0.f;
            }
            uint4 ph, pl;
            split_pack(v, (uint32_t*)&ph, (uint32_t*)&pl);
            *(uint4*)((char*)&sA[0][row][0] + c8 * 2) = ph;
            *(uint4*)((char*)&sA[1][row][0] + c8 * 2) = pl;

            const int gn = colBase + row;         // < Nc always
            const char* pbh = (const char*)Bhi + ((size_t)gn * K + k0) * 2 + c8 * 2;
            const char* pbl = (const char*)Blo + ((size_t)gn * K + k0) * 2 + c8 * 2;
            *(float4*)((char*)&sB[0][row][0] + c8 * 2) = *(const float4*)pbh;
            *(float4*)((char*)&sB[1][row][0] + c8 * 2) = *(const float4*)pbl;
        }
        __syncthreads();

#pragma unroll
        for (int k16 = 0; k16 < 2; k16++) {
            uint32_t ahi[2][4], alo[2][4];
#pragma unroll
            for (int mt = 0; mt < 2; mt++) {
                const uint32_t ra = sAu +
                    (uint32_t)((wm * 32 + mt * 16 + (lane & 15)) * (LDSE * 2)
                               + k16 * 32 + (lane >> 4) * 16);
                ldsm_x4(ahi[mt], ra);
                ldsm_x4(alo[mt], ra + PLANE);
            }
#pragma unroll
            for (int nt = 0; nt < 8; nt++) {
                const uint32_t rb = sBu +
                    (uint32_t)((wn * 64 + nt * 8 + (lane & 7)) * (LDSE * 2)
                               + k16 * 32 + ((lane >> 3) & 1) * 16);
                uint32_t bhi[2], blo[2];
                ldsm_x2(bhi, rb);
                ldsm_x2(blo, rb + PLANE);
#pragma unroll
                for (int mt = 0; mt < 2; mt++) {
                    mma_bf16(acc[mt][nt], ahi[mt], bhi);
                    mma_bf16(acc[mt][nt], ahi[mt], blo);
                    mma_bf16(acc[mt][nt], alo[mt], bhi);
                }
            }
        }
        __syncthreads();
    }

    const int g = lane >> 2, tq = lane & 3;
#pragma unroll
    for (int mt = 0; mt < 2; mt++) {
#pragma unroll
        for (int nt = 0; nt < 8; nt++) {
            const int col = colBase + wn * 64 + nt * 8 + tq * 2;
#pragma unroll
            for (int half = 0; half < 2; half++) {
                const int row = rowBase + wm * 32 + mt * 16 + g + half * 8;
                if (row < M) {
#pragma unroll
                    for (int e = 0; e < 2; e++) {
                        float v = acc[mt][nt][half * 2 + e];
                        const int c = col + e;
                        if (bias) v += bias[c];
                        if (ACT == 1) v = tanhf(v);
                        else if (ACT == 2) v = fmaxf(v, 0.f);
                        C[(size_t)row * Nc + c] = v;
                    }
                }
            }
        }
    }
}

// ---------------- weight transpose + split ----------------
__global__ void cvt_wt(const float* __restrict__ W, __nv_bfloat16* __restrict__ hi,
                       __nv_bfloat16* __restrict__ lo, int K, int N) {
    const int i = blockIdx.x * blockDim.x + threadIdx.x;
    if (i >= K * N) return;
    const int n = i / K, k = i % K;
    const float v = W[k * N + n];
    const __nv_bfloat16 h = __float2bfloat16(v);
    hi[i] = h;
    lo[i] = __float2bfloat16(v - __bfloat162float(h));
}
// batched for 6 GAT layers [256x256] each
__global__ void cvt_wt_gat(const float* __restrict__ W, __nv_bfloat16* __restrict__ hi,
                           __nv_bfloat16* __restrict__ lo) {
    const int i = blockIdx.x * blockDim.x + threadIdx.x;
    if (i >= 6 * 65536) return;
    const int pl = i >> 16, r = i & 65535;
    const int n = r / 256, k = r % 256;
    const float v = W[(size_t)pl * 65536 + k * 256 + n];
    const __nv_bfloat16 h = __float2bfloat16(v);
    hi[i] = h;
    lo[i] = __float2bfloat16(v - __bfloat162float(h));
}

// ---------------- CSR build ----------------
__device__ __forceinline__ int block_incl_scan(int v) {
    const int lane = threadIdx.x & 31, wid = threadIdx.x >> 5;
#pragma unroll
    for (int o = 1; o < 32; o <<= 1) {
        const int u = __shfl_up_sync(0xffffffffu, v, o);
        if (lane >= o) v += u;
    }
    __shared__ int ws[8];
    if (lane == 31) ws[wid] = v;
    __syncthreads();
    if (wid == 0) {
        int s = (lane < 8) ? ws[lane] : 0;
#pragma unroll
        for (int o = 1; o < 8; o <<= 1) {
            const int u = __shfl_up_sync(0xffffffffu, s, o);
            if (lane >= o) s += u;
        }
        if (lane < 8) ws[lane] = s;
    }
    __syncthreads();
    if (wid > 0) v += ws[wid - 1];
    return v;
}
__global__ void deg_init(int* __restrict__ deg) {
    const int i = blockIdx.x * blockDim.x + threadIdx.x;
    if (i < NN) deg[i] = 1;   // self loop
}
__global__ void deg_hist(const int* __restrict__ dst, int* __restrict__ deg) {
    const int e = blockIdx.x * blockDim.x + threadIdx.x;
    if (e < EE) atomicAdd(&deg[dst[e]], 1);
}
__global__ void scan1(const int* __restrict__ deg, int* __restrict__ bsum) {
    const int i = blockIdx.x * 256 + threadIdx.x;
    const int inc = block_incl_scan((i < NN) ? deg[i] : 0);
    if (threadIdx.x == 255) bsum[blockIdx.x] = inc;
}
__global__ void scan2(const int* __restrict__ bsum, int* __restrict__ boff,
                      int* __restrict__ rowptr) {
    const int t = threadIdx.x;
    const int v = (t < NBLK) ? bsum[t] : 0;
    const int inc = block_incl_scan(v);
    if (t < NBLK) boff[t] = inc - v;
    if (t == 0) rowptr[NN] = ETOT;
}
__global__ void scan3(const int* __restrict__ deg, const int* __restrict__ boff,
                      int* __restrict__ rowptr, int* __restrict__ cursor,
                      int* __restrict__ colidx) {
    const int i = blockIdx.x * 256 + threadIdx.x;
    const int v = (i < NN) ? deg[i] : 0;
    const int inc = block_incl_scan(v);
    if (i < NN) {
        const int r = boff[blockIdx.x] + inc - v;
        rowptr[i] = r;
        cursor[i] = r + 1;
        colidx[r] = i;        // self loop first
    }
}
__global__ void csr_scatter(const int* __restrict__ src, const int* __restrict__ dst,
                            int* __restrict__ cursor, int* __restrict__ colidx) {
    const int e = blockIdx.x * blockDim.x + threadIdx.x;
    if (e >= EE) return;
    const int pos = atomicAdd(&cursor[dst[e]], 1);
    colidx[pos] = src[e];
}

// ---------------- per-node attention logits ----------------
__global__ void node_prep(const float* __restrict__ hp,
                          const float* __restrict__ a_src,
                          const float* __restrict__ a_dst,
                          float* __restrict__ s_src, float* __restrict__ s_dst) {
    const int n = blockIdx.x;
    const int t = threadIdx.x;
    const float v = hp[n * 256 + t];
    float ps = v * a_src[t];
    float pd = v * a_dst[t];
#pragma unroll
    for (int o = 16; o > 0; o >>= 1) {
        ps += __shfl_down_sync(0xffffffffu, ps, o);
        pd += __shfl_down_sync(0xffffffffu, pd, o);
    }
    if ((t & 31) == 0) {
        s_src[n * NH + (t >> 5)] = ps;
        s_dst[n * NH + (t >> 5)] = pd;
    }
}

// ---------------- CSR aggregation: softmax-weighted gather + bias + ELU ----------------
// One warp per dst node. No atomics; denom + output accumulated in registers.
__global__ void gat_aggr(const int* __restrict__ rowptr, const int* __restrict__ colidx,
                         const float* __restrict__ s_src, const float* __restrict__ s_dst,
                         const float* __restrict__ hp, const float* __restrict__ b,
                         float* __restrict__ outp, int rowStride) {
    const int n = (blockIdx.x * blockDim.x + threadIdx.x) >> 5;
    const int lane = threadIdx.x & 31;
    if (n >= NN) return;
    const float sd = (lane < 8) ? s_dst[n * NH + lane] : 0.f;
    const int e0 = rowptr[n], e1 = rowptr[n + 1];
    float acc[8] = {0.f, 0.f, 0.f, 0.f, 0.f, 0.f, 0.f, 0.f};
    float den = 0.f;
    for (int e = e0; e < e1; e++) {
        const int s = colidx[e];
        float ex = 0.f;
        if (lane < 8) {
            const float zz = __ldg(&s_src[s * NH + lane]) + sd;
            const float l = zz > 0.f ? zz : 0.2f * zz;
            ex = __expf(l);
            den += ex;
        }
        float a[8];
#pragma unroll
        for (int h = 0; h < 8; h++) a[h] = __shfl_sync(0xffffffffu, ex, h);
        const float* row = hp + (size_t)s * 256;
#pragma unroll
        for (int h = 0; h < 8; h++) acc[h] += a[h] * __ldg(&row[h * 32 + lane]);
    }
#pragma unroll
    for (int h = 0; h < 8; h++) {
        const float dh = __shfl_sync(0xffffffffu, den, h);
        const int t = h * 32 + lane;
        float v = acc[h] / dh + b[t];
        v = v > 0.f ? v : expm1f(v);
        outp[(size_t)n * rowStride + t] = v;
    }
}

// ---------------- semantic attention ----------------
__global__ void sem_kernel(const float* __restrict__ hid, const float* __restrict__ W2,
                           const float* __restrict__ emb, float* __restrict__ z) {
    const int warp = (blockIdx.x * blockDim.x + threadIdx.x) >> 5;
    const int lane = threadIdx.x & 31;
    if (warp >= NN) return;
    float sc[3];
#pragma unroll
    for (int p = 0; p < 3; p++) {
        float part = 0.f;
#pragma unroll
        for (int t = lane; t < 128; t += 32)
            part += hid[(size_t)(warp * 3 + p) * 128 + t] * W2[t];
#pragma unroll
        for (int o = 16; o > 0; o >>= 1) part += __shfl_down_sync(0xffffffffu, part, o);
        sc[p] = __shfl_sync(0xffffffffu, part, 0);
    }
    const float mx = fmaxf(sc[0], fmaxf(sc[1], sc[2]));
    const float e0 = __expf(sc[0] - mx), e1 = __expf(sc[1] - mx), e2 = __expf(sc[2] - mx);
    const float inv = 1.f / (e0 + e1 + e2);
    const float w0 = e0 * inv, w1 = e1 * inv, w2 = e2 * inv;
    const float* er = &emb[(size_t)warp * 768];
#pragma unroll
    for (int j = lane; j < 256; j += 32)
        z[(size_t)warp * 256 + j] = w0 * er[j] + w1 * er[256 + j] + w2 * er[512 + j];
}

// ---------------- classifier head ----------------
__global__ void cls_final(const float* __restrict__ hcls, const float* __restrict__ W2,
                          const float* __restrict__ b2, float* __restrict__ out) {
    const int warp = (blockIdx.x * blockDim.x + threadIdx.x) >> 5;
    const int lane = threadIdx.x & 31;
    if (warp >= NN) return;
    float p0 = 0.f, p1 = 0.f;
#pragma unroll
    for (int t = lane; t < 128; t += 32) {
        const float v = hcls[(size_t)warp * 128 + t];
        p0 += v * W2[t * 2 + 0];
        p1 += v * W2[t * 2 + 1];
    }
#pragma unroll
    for (int o = 16; o > 0; o >>= 1) {
        p0 += __shfl_down_sync(0xffffffffu, p0, o);
        p1 += __shfl_down_sync(0xffffffffu, p1, o);
    }
    if (lane == 0) {
        out[(size_t)warp * 2 + 0] = p0 + b2[0];
        out[(size_t)warp * 2 + 1] = p1 + b2[1];
    }
}

extern "C" void kernel_launch(void* const* d_in, const int* in_sizes, int n_in,
                              void* d_out, int out_size) {
    const float* x        = (const float*)d_in[0];
    const int*   edges    = (const int*)  d_in[1];
    const float* proj_W   = (const float*)d_in[2];
    const float* proj_b   = (const float*)d_in[3];
    const float* gat_W    = (const float*)d_in[4];
    const float* gat_asrc = (const float*)d_in[5];
    const float* gat_adst = (const float*)d_in[6];
    const float* gat_b    = (const float*)d_in[7];
    const float* sem_W1   = (const float*)d_in[8];
    const float* sem_b1   = (const float*)d_in[9];
    const float* sem_W2   = (const float*)d_in[10];
    const float* cls_W1   = (const float*)d_in[11];
    const float* cls_b1   = (const float*)d_in[12];
    const float* cls_W2   = (const float*)d_in[13];
    const float* cls_b2   = (const float*)d_in[14];
    float* out = (float*)d_out;

    float *h0, *h, *hp, *ssrc, *sdst, *emb, *hid, *z, *hcls;
    __nv_bfloat16 *whi, *wlo;
    int *rowptr, *colidx, *deg, *cursor, *bsum, *boff;
    cudaGetSymbolAddress((void**)&h0,     g_h0);
    cudaGetSymbolAddress((void**)&h,      g_h);
    cudaGetSymbolAddress((void**)&hp,     g_hp);
    cudaGetSymbolAddress((void**)&ssrc,   g_ssrc);
    cudaGetSymbolAddress((void**)&sdst,   g_sdst);
    cudaGetSymbolAddress((void**)&emb,    g_emb);
    cudaGetSymbolAddress((void**)&hid,    g_hid);
    cudaGetSymbolAddress((void**)&z,      g_z);
    cudaGetSymbolAddress((void**)&hcls,   g_hcls);
    cudaGetSymbolAddress((void**)&whi,    g_whi);
    cudaGetSymbolAddress((void**)&wlo,    g_wlo);
    cudaGetSymbolAddress((void**)&rowptr, g_rowptr);
    cudaGetSymbolAddress((void**)&colidx, g_colidx);
    cudaGetSymbolAddress((void**)&deg,    g_deg);
    cudaGetSymbolAddress((void**)&cursor, g_cursor);
    cudaGetSymbolAddress((void**)&bsum,   g_bsum);
    cudaGetSymbolAddress((void**)&boff,   g_boff);

    const int OFF_PROJ = 0;
    const int OFF_GAT  = 32768;
    const int OFF_SEM  = 32768 + 6 * 65536;
    const int OFF_CLS  = OFF_SEM + 32768;

    // weight transpose + split
    cvt_wt<<<(128 * 256 + 255) / 256, 256>>>(proj_W, whi + OFF_PROJ, wlo + OFF_PROJ, 128, 256);
    cvt_wt_gat<<<(6 * 65536 + 255) / 256, 256>>>(gat_W, whi + OFF_GAT, wlo + OFF_GAT);
    cvt_wt<<<(256 * 128 + 255) / 256, 256>>>(sem_W1, whi + OFF_SEM, wlo + OFF_SEM, 256, 128);
    cvt_wt<<<(256 * 128 + 255) / 256, 256>>>(cls_W1, whi + OFF_CLS, wlo + OFF_CLS, 256, 128);

    // CSR build for 3 metapaths
    const int eBlocks = (EE + 255) / 256;
    for (int p = 0; p < 3; p++) {
        const int* srcp = edges + (size_t)p * 2 * EE;
        const int* dstp = srcp + EE;
        int* rp = rowptr + p * (NN + 1);
        int* ci = colidx + (size_t)p * ETOT;
        deg_init<<<NBLK, 256>>>(deg);
        deg_hist<<<eBlocks, 256>>>(dstp, deg);
        scan1<<<NBLK, 256>>>(deg, bsum);
        scan2<<<1, 256>>>(bsum, boff, rp);
        scan3<<<NBLK, 256>>>(deg, boff, rp, cursor, ci);
        csr_scatter<<<eBlocks, 256>>>(srcp, dstp, cursor, ci);
    }

    const int warpNodeBlocks = (NN * 32 + 255) / 256;  // 6250
    const dim3 gProj(2, (NN + 127) / 128);
    const dim3 gGat(2, (NN + 127) / 128);
    const dim3 gSem(1, (3 * NN + 127) / 128);
    const dim3 gCls(1, (NN + 127) / 128);

    // proj: h0 = x @ proj_W + proj_b
    gemm_mma<0><<<gProj, 256>>>(x, whi + OFF_PROJ, wlo + OFF_PROJ, proj_b, h0, NN, 128, 256);

    for (int p = 0; p < 3; p++) {
        const int* rp = rowptr + p * (NN + 1);
        const int* ci = colidx + (size_t)p * ETOT;
        for (int l = 0; l < 2; l++) {
            const int pl = p * 2 + l;
            const float* hin = (l == 0) ? h0 : h;
            gemm_mma<0><<<gGat, 256>>>(hin, whi + OFF_GAT + pl * 65536,
                                       wlo + OFF_GAT + pl * 65536,
                                       nullptr, hp, NN, 256, 256);
            node_prep<<<NN, 256>>>(hp, gat_asrc + pl * 256, gat_adst + pl * 256, ssrc, sdst);
            float* outp = (l == 0) ? h : (emb + p * 256);
            const int stride = (l == 0) ? 256 : 768;
            gat_aggr<<<warpNodeBlocks, 256>>>(rp, ci, ssrc, sdst, hp,
                                              gat_b + pl * 256, outp, stride);
        }
    }

    // semantic attention
    gemm_mma<1><<<gSem, 256>>>(emb, whi + OFF_SEM, wlo + OFF_SEM, sem_b1, hid, 3 * NN, 256, 128);
    sem_kernel<<<warpNodeBlocks, 256>>>(hid, sem_W2, emb, z);

    // classifier
    gemm_mma<2><<<gCls, 256>>>(z, whi + OFF_CLS, wlo + OFF_CLS, cls_b1, hcls, NN, 256, 128);
    cls_final<<<warpNodeBlocks, 256>>>(hcls, cls_W2, cls_b2, out);
}